// round 1
// baseline (speedup 1.0000x reference)
#include <cuda_runtime.h>

// MLP_RSNA6: out[b, v[g,t]] = relu(sum_i x[b, k[g,i]] * w1[i] + b1) * w2[t] + b2[t]
// B=500000, TOTAL_IN=200, GROUPS=25, IN_NUM=8, OUT=75.
//
// Strategy (HBM-bound, 550 MB total traffic):
//  - Block stages 128 rows of x (200 f32 each) into smem via fully coalesced
//    float4 loads; smem row stride 201 (odd) => conflict-free indexed gather.
//  - Each thread computes one row's 75 outputs into registers (full unroll),
//    scatters them back into its own smem row (conflict-free), then the block
//    writes the packed 75-wide output rows to gmem fully coalesced.

#define TPB     128
#define ROWSPB  128
#define NCOLS   200
#define SSTRIDE 201
#define NGROUPS 25
#define IN_NUM  8
#define NOUT    75

#define SMEM_BYTES (ROWSPB * SSTRIDE * 4 + NGROUPS * IN_NUM * 4 + NGROUPS * 3 * 4)

__global__ __launch_bounds__(TPB, 2)
void mlp_rsna6_kernel(const float* __restrict__ x,
                      const float* __restrict__ w1,
                      const float* __restrict__ b1,
                      const float* __restrict__ w2,
                      const float* __restrict__ b2,
                      const int* __restrict__ kidx,
                      const int* __restrict__ vidx,
                      float* __restrict__ out,
                      int B)
{
    extern __shared__ float smem[];
    float* sx = smem;                                  // [ROWSPB * SSTRIDE]
    int*   sk = (int*)(smem + ROWSPB * SSTRIDE);       // [200]
    int*   sv = sk + NGROUPS * IN_NUM;                 // [75]

    const int tid  = threadIdx.x;
    const int row0 = blockIdx.x * ROWSPB;
    const int nrows = min(ROWSPB, B - row0);

    // ---- Stage indices ----
    for (int e = tid; e < NGROUPS * IN_NUM; e += TPB) sk[e] = kidx[e];
    for (int e = tid; e < NGROUPS * 3;      e += TPB) sv[e] = vidx[e];

    // ---- Stage x rows: coalesced float4 loads, scalar smem stores (padded) ----
    {
        const float4* x4 = reinterpret_cast<const float4*>(x + (long long)row0 * NCOLS);
        const int total4 = nrows * (NCOLS / 4);        // nrows * 50
        for (int e = tid; e < total4; e += TPB) {
            float4 val = x4[e];
            int le = e * 4;
            int r  = le / NCOLS;                        // const-div -> mul
            int c  = le - r * NCOLS;
            float* dst = &sx[r * SSTRIDE + c];
            dst[0] = val.x; dst[1] = val.y; dst[2] = val.z; dst[3] = val.w;
        }
    }

    // ---- Weights to registers (broadcast, L1-resident) ----
    float w1r[IN_NUM];
#pragma unroll
    for (int i = 0; i < IN_NUM; i++) w1r[i] = __ldg(&w1[i]);
    const float b1r = __ldg(&b1[0]);
    float w2r[3], b2r[3];
#pragma unroll
    for (int t = 0; t < 3; t++) { w2r[t] = __ldg(&w2[t]); b2r[t] = __ldg(&b2[t]); }

    __syncthreads();

    // ---- Compute: one thread per row, results into registers ----
    float o[NGROUPS * 3];
    if (tid < nrows) {
        const float* xr = &sx[tid * SSTRIDE];
#pragma unroll
        for (int g = 0; g < NGROUPS; g++) {
            float h = b1r;
#pragma unroll
            for (int i = 0; i < IN_NUM; i++)
                h = fmaf(xr[sk[g * IN_NUM + i]], w1r[i], h);
            h = fmaxf(h, 0.0f);
#pragma unroll
            for (int t = 0; t < 3; t++)
                o[g * 3 + t] = fmaf(h, w2r[t], b2r[t]);
        }
    }

    __syncthreads();   // all x reads done before we overwrite the staging rows

    // ---- Scatter outputs into own smem row (conflict-free: odd stride) ----
    if (tid < nrows) {
        float* orow = &sx[tid * SSTRIDE];
#pragma unroll
        for (int j = 0; j < NGROUPS * 3; j++)
            orow[sv[j]] = o[j];
    }

    __syncthreads();

    // ---- Coalesced writeout of packed 75-wide rows ----
    {
        float* outp = out + (long long)row0 * NOUT;
        const int ototal = nrows * NOUT;
        for (int e = tid; e < ototal; e += TPB) {
            int r = e / NOUT;
            int j = e - r * NOUT;
            outp[e] = sx[r * SSTRIDE + j];
        }
    }
}

extern "C" void kernel_launch(void* const* d_in, const int* in_sizes, int n_in,
                              void* d_out, int out_size)
{
    const float* x    = (const float*)d_in[0];
    const float* w1   = (const float*)d_in[1];
    const float* b1   = (const float*)d_in[2];
    const float* w2   = (const float*)d_in[3];
    const float* b2   = (const float*)d_in[4];
    const int*   kidx = (const int*)d_in[5];
    const int*   vidx = (const int*)d_in[6];
    float* out = (float*)d_out;

    const int B = in_sizes[0] / NCOLS;
    const int grid = (B + ROWSPB - 1) / ROWSPB;

    cudaFuncSetAttribute(mlp_rsna6_kernel,
                         cudaFuncAttributeMaxDynamicSharedMemorySize, SMEM_BYTES);

    mlp_rsna6_kernel<<<grid, TPB, SMEM_BYTES>>>(x, w1, b1, w2, b2, kidx, vidx, out, B);
}

// round 4
// speedup vs baseline: 3.1982x; 3.1982x over previous
#include <cuda_runtime.h>

// MLP_RSNA6: out[b, v[g,t]] = relu(sum_i x[b, k[g,i]] * w1[i] + b1) * w2[t] + b2[t]
// B=500000, TOTAL_IN=200, GROUPS=25, IN_NUM=8, OUT=75.
//
// Key observation: in this dataset k = arange(200).reshape(25,8) and
// v = arange(75).reshape(25,3) (identity gather/scatter). Then task
// t = row*25+g reads x4[2t], x4[2t+1] (32 contiguous bytes) and writes
// out[3t..3t+2] (12 contiguous bytes) -> fully coalesced, no smem, no
// barriers, full occupancy. We VERIFY this at runtime from the index
// tensors and fall back to a general (slower but correct) path otherwise.

#define TPB 256
#define NGROUPS 25
#define IN_NUM  8
#define NCOLS   200
#define NOUT    75

__global__ __launch_bounds__(TPB)
void mlp_rsna6_fused(const float* __restrict__ x,
                     const float* __restrict__ w1,
                     const float* __restrict__ b1,
                     const float* __restrict__ w2,
                     const float* __restrict__ b2,
                     const int* __restrict__ kidx,
                     const int* __restrict__ vidx,
                     float* __restrict__ out,
                     int B)
{
    // ---- runtime identity-permutation check (block-local, cheap) ----
    __shared__ int s_ok;
    if (threadIdx.x == 0) s_ok = 1;
    __syncthreads();
    {
        bool bad = false;
        for (int e = threadIdx.x; e < NGROUPS * IN_NUM; e += TPB)
            bad |= (__ldg(&kidx[e]) != e);
        for (int e = threadIdx.x; e < NGROUPS * 3; e += TPB)
            bad |= (__ldg(&vidx[e]) != e);
        if (bad) s_ok = 0;
    }
    __syncthreads();

    // ---- weights to registers (broadcast, L1-resident) ----
    float w1r[IN_NUM];
#pragma unroll
    for (int i = 0; i < IN_NUM; i++) w1r[i] = __ldg(&w1[i]);
    const float b1r = __ldg(&b1[0]);
    float w2r[3], b2r[3];
#pragma unroll
    for (int t = 0; t < 3; t++) { w2r[t] = __ldg(&w2[t]); b2r[t] = __ldg(&b2[t]); }

    if (s_ok) {
        // ================= FAST PATH (identity indices) =================
        // task t in [0, B*25): row = t/25, g = t%25.
        // reads  x4[2t], x4[2t+1]  (32B contiguous per lane)
        // writes out[3t .. 3t+2]   (12B contiguous per lane)
        const float4* x4 = reinterpret_cast<const float4*>(x);
        const int NT = B * NGROUPS;
        const int stride = gridDim.x * TPB;
        int base = blockIdx.x * TPB + threadIdx.x;

        for (; base < NT; base += 4 * stride) {
            float4 a0[4], a1[4];
            int tt[4];
#pragma unroll
            for (int j = 0; j < 4; j++) {
                int t = base + j * stride;
                tt[j] = t;
                if (t < NT) {
                    a0[j] = __ldcs(&x4[2 * t]);
                    a1[j] = __ldcs(&x4[2 * t + 1]);
                }
            }
#pragma unroll
            for (int j = 0; j < 4; j++) {
                int t = tt[j];
                if (t < NT) {
                    float h = b1r;
                    h = fmaf(a0[j].x, w1r[0], h);
                    h = fmaf(a0[j].y, w1r[1], h);
                    h = fmaf(a0[j].z, w1r[2], h);
                    h = fmaf(a0[j].w, w1r[3], h);
                    h = fmaf(a1[j].x, w1r[4], h);
                    h = fmaf(a1[j].y, w1r[5], h);
                    h = fmaf(a1[j].z, w1r[6], h);
                    h = fmaf(a1[j].w, w1r[7], h);
                    h = fmaxf(h, 0.0f);
                    __stcs(&out[3 * t + 0], fmaf(h, w2r[0], b2r[0]));
                    __stcs(&out[3 * t + 1], fmaf(h, w2r[1], b2r[1]));
                    __stcs(&out[3 * t + 2], fmaf(h, w2r[2], b2r[2]));
                }
            }
        }
    } else {
        // ============ GENERAL FALLBACK (arbitrary indices) ============
        // Thread per row, direct (strided) loads. Correct for any k/v.
        const int stride = gridDim.x * TPB;
        for (int r = blockIdx.x * TPB + threadIdx.x; r < B; r += stride) {
            const float* xr = x + (long long)r * NCOLS;
            float* orow = out + (long long)r * NOUT;
            // reference initializes out to zeros before scatter
#pragma unroll 5
            for (int j = 0; j < NOUT; j++) orow[j] = 0.0f;
#pragma unroll 1
            for (int g = 0; g < NGROUPS; g++) {
                float h = b1r;
#pragma unroll
                for (int i = 0; i < IN_NUM; i++)
                    h = fmaf(__ldg(&xr[__ldg(&kidx[g * IN_NUM + i])]), w1r[i], h);
                h = fmaxf(h, 0.0f);
#pragma unroll
                for (int t = 0; t < 3; t++)
                    orow[__ldg(&vidx[g * 3 + t])] = fmaf(h, w2r[t], b2r[t]);
            }
        }
    }
}

extern "C" void kernel_launch(void* const* d_in, const int* in_sizes, int n_in,
                              void* d_out, int out_size)
{
    const float* x    = (const float*)d_in[0];
    const float* w1   = (const float*)d_in[1];
    const float* b1   = (const float*)d_in[2];
    const float* w2   = (const float*)d_in[3];
    const float* b2   = (const float*)d_in[4];
    const int*   kidx = (const int*)d_in[5];
    const int*   vidx = (const int*)d_in[6];
    float* out = (float*)d_out;

    const int B  = in_sizes[0] / NCOLS;
    const long long NT = (long long)B * NGROUPS;
    // ~8 tasks per thread
    int grid = (int)((NT + (long long)TPB * 8 - 1) / ((long long)TPB * 8));
    if (grid < 1) grid = 1;

    mlp_rsna6_fused<<<grid, TPB>>>(x, w1, b1, w2, b2, kidx, vidx, out, B);
}